// round 14
// baseline (speedup 1.0000x reference)
#include <cuda_runtime.h>
#include <cuda_bf16.h>
#include <math.h>
#include <stdint.h>

// Problem shape (fixed by the dataset)
#define BB 8
#define SS 2048
#define DD 1024

// Pre-split bf16 operand arrays (device globals — allocation-guard-safe)
__device__ __nv_bfloat16 g_xhi[(size_t)BB * SS * DD];
__device__ __nv_bfloat16 g_xlo[(size_t)BB * SS * DD];
__device__ __nv_bfloat16 g_xthi[(size_t)BB * SS * DD];
__device__ __nv_bfloat16 g_xtlo[(size_t)BB * SS * DD];
__device__ __nv_bfloat16 g_whi[(size_t)DD * DD];
__device__ __nv_bfloat16 g_wlo[(size_t)DD * DD];
__device__ __nv_bfloat16 g_phi[(size_t)BB * SS * DD];
__device__ __nv_bfloat16 g_plo[(size_t)BB * SS * DD];
__device__ __nv_bfloat16 g_ahi[(size_t)BB * SS * SS];
__device__ __nv_bfloat16 g_alo[(size_t)BB * SS * SS];

// ============================================================
// R14 GEMM: R13 (128x64 CTA tile, BK=16, 3 CTAs/SM, 32x32 warp tiles,
// hoisted ALU) with LSU de-bursting:
//   - cp.async issue moved AFTER the head LDSM pair (aFh+bFh)
//   - bFl LDSM deferred until after burst 1, aFl after burst 2
//   - 5-stage ring (60KB) with WAIT3 (prefetch depth +1)
// ============================================================

#define AH_OFF 0
#define AL_OFF 4096
#define BH_OFF 8192
#define BL_OFF 10240
#define STAGE_B 12288
#define NSTAGE 5
#define GEMM_SMEM (NSTAGE * STAGE_B)   // 60 KB (>= epilogue's 34.8 KB)

__device__ __forceinline__ uint32_t smem_u32(const void* p) {
    uint32_t a;
    asm("{ .reg .u64 t; cvta.to.shared.u64 t, %1; cvt.u32.u64 %0, t; }" : "=r"(a) : "l"(p));
    return a;
}
__device__ __forceinline__ uint32_t sw32(uint32_t off) {
    return off ^ ((off >> 3) & 0x10);
}
__device__ __forceinline__ void ldsm_x4(uint32_t& r0, uint32_t& r1, uint32_t& r2, uint32_t& r3,
                                        uint32_t addr) {
    asm volatile("ldmatrix.sync.aligned.m8n8.x4.shared.b16 {%0,%1,%2,%3}, [%4];"
                 : "=r"(r0), "=r"(r1), "=r"(r2), "=r"(r3) : "r"(addr));
}
__device__ __forceinline__ void mma16816(float* d, const uint32_t* a, const uint32_t* b) {
    asm volatile(
        "mma.sync.aligned.m16n8k16.row.col.f32.bf16.bf16.f32 "
        "{%0,%1,%2,%3}, {%4,%5,%6,%7}, {%8,%9}, {%0,%1,%2,%3};"
        : "+f"(d[0]), "+f"(d[1]), "+f"(d[2]), "+f"(d[3])
        : "r"(a[0]), "r"(a[1]), "r"(a[2]), "r"(a[3]), "r"(b[0]), "r"(b[1]));
}

#define CP_ASYNC16(dst, src) \
    asm volatile("cp.async.cg.shared.global [%0], [%1], 16;" :: "r"(dst), "l"(src) : "memory")
#define CP_COMMIT()  asm volatile("cp.async.commit_group;" ::: "memory")
#define CP_WAIT3()   asm volatile("cp.async.wait_group 3;" ::: "memory")
#define CP_WAIT0()   asm volatile("cp.async.wait_group 0;" ::: "memory")

__device__ __forceinline__ void split2(const float4& v, uint2& hi, uint2& lo) {
    __nv_bfloat162 h0 = __floats2bfloat162_rn(v.x, v.y);
    __nv_bfloat162 h1 = __floats2bfloat162_rn(v.z, v.w);
    float r0 = v.x - __bfloat162float(__low2bfloat16(h0));
    float r1 = v.y - __bfloat162float(__high2bfloat16(h0));
    float r2 = v.z - __bfloat162float(__low2bfloat16(h1));
    float r3 = v.w - __bfloat162float(__high2bfloat16(h1));
    __nv_bfloat162 l0 = __floats2bfloat162_rn(r0, r1);
    __nv_bfloat162 l1 = __floats2bfloat162_rn(r2, r3);
    hi.x = *reinterpret_cast<uint32_t*>(&h0);
    hi.y = *reinterpret_cast<uint32_t*>(&h1);
    lo.x = *reinterpret_cast<uint32_t*>(&l0);
    lo.y = *reinterpret_cast<uint32_t*>(&l1);
}

__global__ __launch_bounds__(256, 3) void gemm_nt_mma(
    const __nv_bfloat16* __restrict__ Ahi, const __nv_bfloat16* __restrict__ Alo,
    const __nv_bfloat16* __restrict__ Bhi, const __nv_bfloat16* __restrict__ Blo,
    float* __restrict__ C, __nv_bfloat16* __restrict__ Chi, __nv_bfloat16* __restrict__ Clo,
    const float* __restrict__ bias,
    int M, int N, int K,
    long long strA, long long strB, long long strC)
{
    extern __shared__ __align__(1024) char smem[];
    const uint32_t sb = smem_u32(smem);
    const int tid = threadIdx.x, wid = tid >> 5, lane = tid & 31;
    const int row0 = blockIdx.y * 128, col0 = blockIdx.x * 64;

    Ahi += (size_t)blockIdx.z * strA;  Alo += (size_t)blockIdx.z * strA;
    Bhi += (size_t)blockIdx.z * strB;  Blo += (size_t)blockIdx.z * strB;

    // 4m x 2n warp grid, 32x32 warp tiles
    const int wm = wid & 3, wn = wid >> 2;
    const int m0w = wm * 32, n0w = wn * 32;

    // ---- cp.async loader indexing (BK=16 -> 32B rows) ----
    const int la_row = tid >> 1;
    const int la_s   = tid & 1;
    const int lb_row = (tid & 127) >> 1;
    const int lb_s   = tid & 1;
    const bool do_b  = (tid < 128);

    // Hoisted: global pointers as u64 (cvta once)
    const unsigned long long pah = (unsigned long long)__cvta_generic_to_global(
        (const void*)(Ahi + (size_t)(row0 + la_row) * K + la_s * 8));
    const unsigned long long pal = (unsigned long long)__cvta_generic_to_global(
        (const void*)(Alo + (size_t)(row0 + la_row) * K + la_s * 8));
    const unsigned long long pbh = (unsigned long long)__cvta_generic_to_global(
        (const void*)(Bhi + (size_t)(col0 + lb_row) * K + lb_s * 8));
    const unsigned long long pbl = (unsigned long long)__cvta_generic_to_global(
        (const void*)(Blo + (size_t)(col0 + lb_row) * K + lb_s * 8));

    // Hoisted: swizzled store offsets
    const uint32_t swa = sw32((uint32_t)(la_row * 32 + la_s * 16));
    const uint32_t swb = sw32((uint32_t)(lb_row * 32 + lb_s * 16));

    // Hoisted: ldmatrix swizzled offsets (loop-invariant)
    const uint32_t a_lrow = (uint32_t)(lane & 15);
    const uint32_t a_lc16 = (uint32_t)(lane >> 4) * 16;
    const uint32_t b_lrow = (uint32_t)((lane & 7) + ((lane >> 4) & 1) * 8);
    const uint32_t b_lk16 = (uint32_t)((lane >> 3) & 1) * 16;
    const uint32_t offA0 = sw32((uint32_t)((m0w + a_lrow) * 32 + a_lc16));
    const uint32_t offA1 = sw32((uint32_t)((m0w + 16 + a_lrow) * 32 + a_lc16));
    const uint32_t offB0 = sw32((uint32_t)((n0w + b_lrow) * 32 + b_lk16));
    const uint32_t offB1 = sw32((uint32_t)((n0w + 16 + b_lrow) * 32 + b_lk16));

    float acc[2][4][4];
#pragma unroll
    for (int i = 0; i < 2; i++)
#pragma unroll
        for (int j = 0; j < 4; j++)
#pragma unroll
            for (int q = 0; q < 4; q++) acc[i][j][q] = 0.f;

    const int NCH = K >> 4;   // BK=16; 64 or 128 (divisible by NSTAGE-loop handling below)

    auto issue = [&](int ch, uint32_t st) {
        if (ch < NCH) {
            const unsigned long long koff = (unsigned long long)(ch << 5);  // bytes
            CP_ASYNC16(st + AH_OFF + swa, pah + koff);
            CP_ASYNC16(st + AL_OFF + swa, pal + koff);
            if (do_b) {
                CP_ASYNC16(st + BH_OFF + swb, pbh + koff);
                CP_ASYNC16(st + BL_OFF + swb, pbl + koff);
            }
        }
        CP_COMMIT();
    };

    // One chunk: head LDSM (aFh,bFh) -> [issue prefetch] -> burst1 ->
    // ldsm bFl -> burst2 -> ldsm aFl -> burst3.
    auto mma_ks = [&](uint32_t base, int pf_ch, uint32_t pf_st) {
        uint32_t aFh[2][4], bFh[4][2];
        ldsm_x4(aFh[0][0], aFh[0][1], aFh[0][2], aFh[0][3], base + AH_OFF + offA0);
        ldsm_x4(aFh[1][0], aFh[1][1], aFh[1][2], aFh[1][3], base + AH_OFF + offA1);
        {
            uint32_t r0, r1, r2, r3;
            ldsm_x4(r0, r1, r2, r3, base + BH_OFF + offB0);
            bFh[0][0] = r0; bFh[0][1] = r1; bFh[1][0] = r2; bFh[1][1] = r3;
            ldsm_x4(r0, r1, r2, r3, base + BH_OFF + offB1);
            bFh[2][0] = r0; bFh[2][1] = r1; bFh[3][0] = r2; bFh[3][1] = r3;
        }
        // prefetch cp.async AFTER head ldsm (off the critical ldsm->mma path)
        issue(pf_ch, pf_st);
        // burst 1: hh
#pragma unroll
        for (int mf = 0; mf < 2; mf++)
#pragma unroll
            for (int nf = 0; nf < 4; nf++) mma16816(acc[mf][nf], aFh[mf], bFh[nf]);
        // ldsm bFl (needed only for burst 2)
        uint32_t bFl[4][2];
        {
            uint32_t r0, r1, r2, r3;
            ldsm_x4(r0, r1, r2, r3, base + BL_OFF + offB0);
            bFl[0][0] = r0; bFl[0][1] = r1; bFl[1][0] = r2; bFl[1][1] = r3;
            ldsm_x4(r0, r1, r2, r3, base + BL_OFF + offB1);
            bFl[2][0] = r0; bFl[2][1] = r1; bFl[3][0] = r2; bFl[3][1] = r3;
        }
        // burst 2: hi(A) * lo(B)
#pragma unroll
        for (int mf = 0; mf < 2; mf++)
#pragma unroll
            for (int nf = 0; nf < 4; nf++) mma16816(acc[mf][nf], aFh[mf], bFl[nf]);
        // ldsm aFl, burst 3: lo(A) * hi(B)
        uint32_t aFl[2][4];
        ldsm_x4(aFl[0][0], aFl[0][1], aFl[0][2], aFl[0][3], base + AL_OFF + offA0);
        ldsm_x4(aFl[1][0], aFl[1][1], aFl[1][2], aFl[1][3], base + AL_OFF + offA1);
#pragma unroll
        for (int mf = 0; mf < 2; mf++)
#pragma unroll
            for (int nf = 0; nf < 4; nf++) mma16816(acc[mf][nf], aFl[mf], bFh[nf]);
    };

    // prologue: 4 stages in flight
    const uint32_t stages[NSTAGE] = {sb, sb + STAGE_B, sb + 2 * STAGE_B,
                                     sb + 3 * STAGE_B, sb + 4 * STAGE_B};
    issue(0, stages[0]);
    issue(1, stages[1]);
    issue(2, stages[2]);
    issue(3, stages[3]);

    int cur_s = 0, pf_s = 4;
    for (int ch = 0; ch < NCH; ch++) {
        CP_WAIT3();            // chunk ch resident (<=3 newer groups pending)
        __syncthreads();       // ring distance 4 > warp drift 1 -> safe
        mma_ks(stages[cur_s], ch + 4, stages[pf_s]);
        cur_s = (cur_s + 1 == NSTAGE) ? 0 : cur_s + 1;
        pf_s  = (pf_s + 1 == NSTAGE) ? 0 : pf_s + 1;
    }
    CP_WAIT0();
    __syncthreads();

    // ---- epilogue: stage accums -> smem [128][68] -> coalesced writes ----
    float* eps = reinterpret_cast<float*>(smem);
    const int g = lane >> 2, c = lane & 3;
#pragma unroll
    for (int mf = 0; mf < 2; mf++)
#pragma unroll
        for (int nf = 0; nf < 4; nf++) {
            int r  = m0w + mf * 16 + g;
            int cc = n0w + nf * 8 + 2 * c;
            *reinterpret_cast<float2*>(&eps[r * 68 + cc]) =
                make_float2(acc[mf][nf][0], acc[mf][nf][1]);
            *reinterpret_cast<float2*>(&eps[(r + 8) * 68 + cc]) =
                make_float2(acc[mf][nf][2], acc[mf][nf][3]);
        }
    __syncthreads();

    if (Chi) {
        __nv_bfloat16* ph = Chi + (size_t)blockIdx.z * strC;
        __nv_bfloat16* pl = Clo + (size_t)blockIdx.z * strC;
#pragma unroll
        for (int it = 0; it < 8; it++) {
            int idx = tid + it * 256;
            int row = idx >> 4;
            int c4  = (idx & 15) << 2;
            float4 v = *reinterpret_cast<float4*>(&eps[row * 68 + c4]);
            float4 bz = *reinterpret_cast<const float4*>(&bias[col0 + c4]);
            v.x += bz.x; v.y += bz.y; v.z += bz.z; v.w += bz.w;
            uint2 hi, lo;
            split2(v, hi, lo);
            size_t o = (size_t)(row0 + row) * N + col0 + c4;
            *reinterpret_cast<uint2*>(&ph[o]) = hi;
            *reinterpret_cast<uint2*>(&pl[o]) = lo;
        }
    } else {
        float* Cb = C + (size_t)blockIdx.z * strC;
#pragma unroll
        for (int it = 0; it < 8; it++) {
            int idx = tid + it * 256;
            int row = idx >> 4;
            int c4  = (idx & 15) << 2;
            float4 v = *reinterpret_cast<float4*>(&eps[row * 68 + c4]);
            *reinterpret_cast<float4*>(&Cb[(size_t)(row0 + row) * N + col0 + c4]) = v;
        }
    }
}

// ============================================================
// prep_x: X -> X_hi/X_lo + XT_hi/XT_lo
// ============================================================
__global__ __launch_bounds__(256) void prep_x(
    const float* __restrict__ X,
    __nv_bfloat16* __restrict__ Xhi, __nv_bfloat16* __restrict__ Xlo,
    __nv_bfloat16* __restrict__ XThi, __nv_bfloat16* __restrict__ XTlo)
{
    __shared__ float t[32][33];
    const int b = blockIdx.z;
    const int s0 = blockIdx.x * 32, d0 = blockIdx.y * 32;
    const size_t bo = (size_t)b * SS * DD;
    const int tx = threadIdx.x, ty = threadIdx.y;
#pragma unroll
    for (int j = 0; j < 4; j++) {
        int s = s0 + ty + 8 * j;
        float v = X[bo + (size_t)s * DD + d0 + tx];
        t[ty + 8 * j][tx] = v;
        __nv_bfloat16 h = __float2bfloat16(v);
        Xhi[bo + (size_t)s * DD + d0 + tx] = h;
        Xlo[bo + (size_t)s * DD + d0 + tx] = __float2bfloat16(v - __bfloat162float(h));
    }
    __syncthreads();
#pragma unroll
    for (int j = 0; j < 4; j++) {
        int d = d0 + ty + 8 * j;
        float v = t[tx][ty + 8 * j];
        __nv_bfloat16 h = __float2bfloat16(v);
        XThi[bo + (size_t)d * SS + s0 + tx] = h;
        XTlo[bo + (size_t)d * SS + s0 + tx] = __float2bfloat16(v - __bfloat162float(h));
    }
}

__global__ __launch_bounds__(256) void split_w(
    const float* __restrict__ W,
    __nv_bfloat16* __restrict__ Whi, __nv_bfloat16* __restrict__ Wlo)
{
    int idx = blockIdx.x * 256 + threadIdx.x;
    float4 v = reinterpret_cast<const float4*>(W)[idx];
    uint2 hi, lo;
    split2(v, hi, lo);
    reinterpret_cast<uint2*>(Whi)[idx] = hi;
    reinterpret_cast<uint2*>(Wlo)[idx] = lo;
}

// ============================================================
// In-place row softmax + split bf16 out
// ============================================================
__device__ __forceinline__ float warp_max(float v) {
#pragma unroll
    for (int o = 16; o > 0; o >>= 1) v = fmaxf(v, __shfl_xor_sync(0xFFFFFFFFu, v, o));
    return v;
}
__device__ __forceinline__ float warp_sum(float v) {
#pragma unroll
    for (int o = 16; o > 0; o >>= 1) v += __shfl_xor_sync(0xFFFFFFFFu, v, o);
    return v;
}

__global__ __launch_bounds__(256) void softmax_rows(
    float* __restrict__ attn,
    __nv_bfloat16* __restrict__ Ahi, __nv_bfloat16* __restrict__ Alo)
{
    __shared__ float red[8];
    const size_t ro = (size_t)blockIdx.x * SS;
    float* row = attn + ro;
    const int tid = threadIdx.x, lane = tid & 31, wid = tid >> 5;

    float4 v[2];
    v[0] = *reinterpret_cast<const float4*>(&row[tid * 4]);
    v[1] = *reinterpret_cast<const float4*>(&row[(tid + 256) * 4]);

    float mx = -INFINITY;
#pragma unroll
    for (int i = 0; i < 2; i++)
        mx = fmaxf(mx, fmaxf(fmaxf(v[i].x, v[i].y), fmaxf(v[i].z, v[i].w)));
    mx = warp_max(mx);
    if (lane == 0) red[wid] = mx;
    __syncthreads();
    if (wid == 0) {
        float t = (lane < 8) ? red[lane] : -INFINITY;
        t = warp_max(t);
        if (lane == 0) red[0] = t;
    }
    __syncthreads();
    mx = red[0];
    __syncthreads();

    float s = 0.f;
#pragma unroll
    for (int i = 0; i < 2; i++) {
        v[i].x = expf(v[i].x - mx); s += v[i].x;
        v[i].y = expf(v[i].y - mx); s += v[i].y;
        v[i].z = expf(v[i].z - mx); s += v[i].z;
        v[i].w = expf(v[i].w - mx); s += v[i].w;
    }
    s = warp_sum(s);
    if (lane == 0) red[wid] = s;
    __syncthreads();
    if (wid == 0) {
        float t = (lane < 8) ? red[lane] : 0.0f;
        t = warp_sum(t);
        if (lane == 0) red[0] = t;
    }
    __syncthreads();
    float inv = 1.0f / red[0];

#pragma unroll
    for (int i = 0; i < 2; i++) { v[i].x *= inv; v[i].y *= inv; v[i].z *= inv; v[i].w *= inv; }
    *reinterpret_cast<float4*>(&row[tid * 4])         = v[0];
    *reinterpret_cast<float4*>(&row[(tid + 256) * 4]) = v[1];

    uint2 hi, lo;
    split2(v[0], hi, lo);
    *reinterpret_cast<uint2*>(&Ahi[ro + tid * 4]) = hi;
    *reinterpret_cast<uint2*>(&Alo[ro + tid * 4]) = lo;
    split2(v[1], hi, lo);
    *reinterpret_cast<uint2*>(&Ahi[ro + (tid + 256) * 4]) = hi;
    *reinterpret_cast<uint2*>(&Alo[ro + (tid + 256) * 4]) = lo;
}

// ============================================================
// kernel_launch
// ============================================================
extern "C" void kernel_launch(void* const* d_in, const int* in_sizes, int n_in,
                              void* d_out, int out_size)
{
    const float* X    = (const float*)d_in[0];
    const float* W    = (const float*)d_in[1];
    const float* bias = (const float*)d_in[2];

    float* ctx  = (float*)d_out;                           // [8,2048,1024]
    float* attn = (float*)d_out + (size_t)BB * SS * DD;    // [8,2048,2048]

    __nv_bfloat16 *xhi, *xlo, *xthi, *xtlo, *whi, *wlo, *phi, *plo, *ahi, *alo;
    cudaGetSymbolAddress((void**)&xhi,  g_xhi);
    cudaGetSymbolAddress((void**)&xlo,  g_xlo);
    cudaGetSymbolAddress((void**)&xthi, g_xthi);
    cudaGetSymbolAddress((void**)&xtlo, g_xtlo);
    cudaGetSymbolAddress((void**)&whi,  g_whi);
    cudaGetSymbolAddress((void**)&wlo,  g_wlo);
    cudaGetSymbolAddress((void**)&phi,  g_phi);
    cudaGetSymbolAddress((void**)&plo,  g_plo);
    cudaGetSymbolAddress((void**)&ahi,  g_ahi);
    cudaGetSymbolAddress((void**)&alo,  g_alo);

    cudaFuncSetAttribute(gemm_nt_mma, cudaFuncAttributeMaxDynamicSharedMemorySize, GEMM_SMEM);

    const long long sXD = (long long)SS * DD;
    const long long sAA = (long long)SS * SS;

    {
        dim3 grid(SS / 32, DD / 32, BB);
        prep_x<<<grid, dim3(32, 8)>>>(X, xhi, xlo, xthi, xtlo);
    }
    split_w<<<(DD * DD / 4) / 256, 256>>>(W, whi, wlo);

    // GEMM1: proj = X * W^T + b  -> split bf16 pair
    {
        dim3 grid(DD / 64, (BB * SS) / 128, 1);
        gemm_nt_mma<<<grid, 256, GEMM_SMEM>>>(xhi, xlo, whi, wlo,
                                              nullptr, phi, plo, bias,
                                              BB * SS, DD, DD, 0, 0, 0);
    }
    // GEMM2: attn[b] = X[b] * proj[b]^T  (fp32 out)
    {
        dim3 grid(SS / 64, SS / 128, BB);
        gemm_nt_mma<<<grid, 256, GEMM_SMEM>>>(xhi, xlo, phi, plo,
                                              attn, nullptr, nullptr, nullptr,
                                              SS, SS, DD, sXD, sXD, sAA);
    }
    softmax_rows<<<BB * SS, 256>>>(attn, ahi, alo);
    // GEMM3: ctx[b] = attn[b] * XT[b]^T  (fp32 out)
    {
        dim3 grid(DD / 64, SS / 128, BB);
        gemm_nt_mma<<<grid, 256, GEMM_SMEM>>>(ahi, alo, xthi, xtlo,
                                              ctx, nullptr, nullptr, nullptr,
                                              SS, DD, SS, sAA, sXD, sXD);
    }
}

// round 15
// speedup vs baseline: 1.6410x; 1.6410x over previous
#include <cuda_runtime.h>
#include <cuda_bf16.h>
#include <math.h>
#include <stdint.h>

// Problem shape (fixed by the dataset)
#define BB 8
#define SS 2048
#define DD 1024

// Pre-split bf16 operand arrays (device globals — allocation-guard-safe)
__device__ __nv_bfloat16 g_xhi[(size_t)BB * SS * DD];
__device__ __nv_bfloat16 g_xlo[(size_t)BB * SS * DD];
__device__ __nv_bfloat16 g_xthi[(size_t)BB * SS * DD];
__device__ __nv_bfloat16 g_xtlo[(size_t)BB * SS * DD];
__device__ __nv_bfloat16 g_whi[(size_t)DD * DD];
__device__ __nv_bfloat16 g_wlo[(size_t)DD * DD];
__device__ __nv_bfloat16 g_phi[(size_t)BB * SS * DD];
__device__ __nv_bfloat16 g_plo[(size_t)BB * SS * DD];
__device__ __nv_bfloat16 g_ahi[(size_t)BB * SS * SS];
__device__ __nv_bfloat16 g_alo[(size_t)BB * SS * SS];

// ============================================================
// R15 GEMM: R13 restored EXACTLY (128x64 CTA tile, BK=16, 4-stage ring,
// compile-time unrolled x4 loop, 3 CTAs/SM, 32x32 warp tiles, hoisted ALU)
// + the safe half of R14: inside mma_ks, cp.async prefetch issued AFTER the
// head LDSM pair, and bFl/aFl LDSMs deferred between MMA bursts.
// All stage bases / offsets remain compile-time constants.
// ============================================================

#define AH_OFF 0
#define AL_OFF 4096
#define BH_OFF 8192
#define BL_OFF 10240
#define STAGE_B 12288
#define GEMM_SMEM (4 * STAGE_B)   // 48 KB (>= epilogue's 34.8 KB)

__device__ __forceinline__ uint32_t smem_u32(const void* p) {
    uint32_t a;
    asm("{ .reg .u64 t; cvta.to.shared.u64 t, %1; cvt.u32.u64 %0, t; }" : "=r"(a) : "l"(p));
    return a;
}
__device__ __forceinline__ uint32_t sw32(uint32_t off) {
    return off ^ ((off >> 3) & 0x10);
}
__device__ __forceinline__ void ldsm_x4(uint32_t& r0, uint32_t& r1, uint32_t& r2, uint32_t& r3,
                                        uint32_t addr) {
    asm volatile("ldmatrix.sync.aligned.m8n8.x4.shared.b16 {%0,%1,%2,%3}, [%4];"
                 : "=r"(r0), "=r"(r1), "=r"(r2), "=r"(r3) : "r"(addr));
}
__device__ __forceinline__ void mma16816(float* d, const uint32_t* a, const uint32_t* b) {
    asm volatile(
        "mma.sync.aligned.m16n8k16.row.col.f32.bf16.bf16.f32 "
        "{%0,%1,%2,%3}, {%4,%5,%6,%7}, {%8,%9}, {%0,%1,%2,%3};"
        : "+f"(d[0]), "+f"(d[1]), "+f"(d[2]), "+f"(d[3])
        : "r"(a[0]), "r"(a[1]), "r"(a[2]), "r"(a[3]), "r"(b[0]), "r"(b[1]));
}

#define CP_ASYNC16(dst, src) \
    asm volatile("cp.async.cg.shared.global [%0], [%1], 16;" :: "r"(dst), "l"(src) : "memory")
#define CP_COMMIT()  asm volatile("cp.async.commit_group;" ::: "memory")
#define CP_WAIT2()   asm volatile("cp.async.wait_group 2;" ::: "memory")
#define CP_WAIT0()   asm volatile("cp.async.wait_group 0;" ::: "memory")

__device__ __forceinline__ void split2(const float4& v, uint2& hi, uint2& lo) {
    __nv_bfloat162 h0 = __floats2bfloat162_rn(v.x, v.y);
    __nv_bfloat162 h1 = __floats2bfloat162_rn(v.z, v.w);
    float r0 = v.x - __bfloat162float(__low2bfloat16(h0));
    float r1 = v.y - __bfloat162float(__high2bfloat16(h0));
    float r2 = v.z - __bfloat162float(__low2bfloat16(h1));
    float r3 = v.w - __bfloat162float(__high2bfloat16(h1));
    __nv_bfloat162 l0 = __floats2bfloat162_rn(r0, r1);
    __nv_bfloat162 l1 = __floats2bfloat162_rn(r2, r3);
    hi.x = *reinterpret_cast<uint32_t*>(&h0);
    hi.y = *reinterpret_cast<uint32_t*>(&h1);
    lo.x = *reinterpret_cast<uint32_t*>(&l0);
    lo.y = *reinterpret_cast<uint32_t*>(&l1);
}

__global__ __launch_bounds__(256, 3) void gemm_nt_mma(
    const __nv_bfloat16* __restrict__ Ahi, const __nv_bfloat16* __restrict__ Alo,
    const __nv_bfloat16* __restrict__ Bhi, const __nv_bfloat16* __restrict__ Blo,
    float* __restrict__ C, __nv_bfloat16* __restrict__ Chi, __nv_bfloat16* __restrict__ Clo,
    const float* __restrict__ bias,
    int M, int N, int K,
    long long strA, long long strB, long long strC)
{
    extern __shared__ __align__(1024) char smem[];
    const uint32_t sb = smem_u32(smem);
    const int tid = threadIdx.x, wid = tid >> 5, lane = tid & 31;
    const int row0 = blockIdx.y * 128, col0 = blockIdx.x * 64;

    Ahi += (size_t)blockIdx.z * strA;  Alo += (size_t)blockIdx.z * strA;
    Bhi += (size_t)blockIdx.z * strB;  Blo += (size_t)blockIdx.z * strB;

    // 4m x 2n warp grid, 32x32 warp tiles
    const int wm = wid & 3, wn = wid >> 2;
    const int m0w = wm * 32, n0w = wn * 32;

    // ---- cp.async loader indexing (BK=16 -> 32B rows) ----
    const int la_row = tid >> 1;
    const int la_s   = tid & 1;
    const int lb_row = (tid & 127) >> 1;
    const int lb_s   = tid & 1;
    const bool do_b  = (tid < 128);

    // Hoisted: global pointers as u64 (cvta once)
    const unsigned long long pah = (unsigned long long)__cvta_generic_to_global(
        (const void*)(Ahi + (size_t)(row0 + la_row) * K + la_s * 8));
    const unsigned long long pal = (unsigned long long)__cvta_generic_to_global(
        (const void*)(Alo + (size_t)(row0 + la_row) * K + la_s * 8));
    const unsigned long long pbh = (unsigned long long)__cvta_generic_to_global(
        (const void*)(Bhi + (size_t)(col0 + lb_row) * K + lb_s * 8));
    const unsigned long long pbl = (unsigned long long)__cvta_generic_to_global(
        (const void*)(Blo + (size_t)(col0 + lb_row) * K + lb_s * 8));

    // Hoisted: swizzled store offsets
    const uint32_t swa = sw32((uint32_t)(la_row * 32 + la_s * 16));
    const uint32_t swb = sw32((uint32_t)(lb_row * 32 + lb_s * 16));

    // Hoisted: ldmatrix swizzled offsets (loop-invariant)
    const uint32_t a_lrow = (uint32_t)(lane & 15);
    const uint32_t a_lc16 = (uint32_t)(lane >> 4) * 16;
    const uint32_t b_lrow = (uint32_t)((lane & 7) + ((lane >> 4) & 1) * 8);
    const uint32_t b_lk16 = (uint32_t)((lane >> 3) & 1) * 16;
    const uint32_t offA0 = sw32((uint32_t)((m0w + a_lrow) * 32 + a_lc16));
    const uint32_t offA1 = sw32((uint32_t)((m0w + 16 + a_lrow) * 32 + a_lc16));
    const uint32_t offB0 = sw32((uint32_t)((n0w + b_lrow) * 32 + b_lk16));
    const uint32_t offB1 = sw32((uint32_t)((n0w + 16 + b_lrow) * 32 + b_lk16));

    // Hoisted: stage base addresses
    const uint32_t stage0 = sb;
    const uint32_t stage1 = sb + STAGE_B;
    const uint32_t stage2 = sb + 2 * STAGE_B;
    const uint32_t stage3 = sb + 3 * STAGE_B;

    float acc[2][4][4];
#pragma unroll
    for (int i = 0; i < 2; i++)
#pragma unroll
        for (int j = 0; j < 4; j++)
#pragma unroll
            for (int q = 0; q < 4; q++) acc[i][j][q] = 0.f;

    const int NCH = K >> 4;   // BK=16; 64 or 128 here (divisible by 4)

    auto issue = [&](int ch, uint32_t st) {
        if (ch < NCH) {
            const unsigned long long koff = (unsigned long long)(ch << 5);  // bytes
            CP_ASYNC16(st + AH_OFF + swa, pah + koff);
            CP_ASYNC16(st + AL_OFF + swa, pal + koff);
            if (do_b) {
                CP_ASYNC16(st + BH_OFF + swb, pbh + koff);
                CP_ASYNC16(st + BL_OFF + swb, pbl + koff);
            }
        }
        CP_COMMIT();
    };

    // One chunk: head LDSM (aFh,bFh) -> [cp.async prefetch] -> burst1 ->
    // ldsm bFl -> burst2 -> ldsm aFl -> burst3.  (R14's safe reorder)
    auto mma_ks = [&](uint32_t base, int pf_ch, uint32_t pf_st) {
        uint32_t aFh[2][4], bFh[4][2];
        ldsm_x4(aFh[0][0], aFh[0][1], aFh[0][2], aFh[0][3], base + AH_OFF + offA0);
        ldsm_x4(aFh[1][0], aFh[1][1], aFh[1][2], aFh[1][3], base + AH_OFF + offA1);
        {
            uint32_t r0, r1, r2, r3;
            ldsm_x4(r0, r1, r2, r3, base + BH_OFF + offB0);
            bFh[0][0] = r0; bFh[0][1] = r1; bFh[1][0] = r2; bFh[1][1] = r3;
            ldsm_x4(r0, r1, r2, r3, base + BH_OFF + offB1);
            bFh[2][0] = r0; bFh[2][1] = r1; bFh[3][0] = r2; bFh[3][1] = r3;
        }
        // prefetch AFTER head ldsm: off the ldsm->mma critical path
        issue(pf_ch, pf_st);
        // burst 1: hh
#pragma unroll
        for (int mf = 0; mf < 2; mf++)
#pragma unroll
            for (int nf = 0; nf < 4; nf++) mma16816(acc[mf][nf], aFh[mf], bFh[nf]);
        // ldsm bFl (needed only for burst 2)
        uint32_t bFl[4][2];
        {
            uint32_t r0, r1, r2, r3;
            ldsm_x4(r0, r1, r2, r3, base + BL_OFF + offB0);
            bFl[0][0] = r0; bFl[0][1] = r1; bFl[1][0] = r2; bFl[1][1] = r3;
            ldsm_x4(r0, r1, r2, r3, base + BL_OFF + offB1);
            bFl[2][0] = r0; bFl[2][1] = r1; bFl[3][0] = r2; bFl[3][1] = r3;
        }
        // burst 2: hi(A) * lo(B)
#pragma unroll
        for (int mf = 0; mf < 2; mf++)
#pragma unroll
            for (int nf = 0; nf < 4; nf++) mma16816(acc[mf][nf], aFh[mf], bFl[nf]);
        // ldsm aFl, burst 3: lo(A) * hi(B)
        uint32_t aFl[2][4];
        ldsm_x4(aFl[0][0], aFl[0][1], aFl[0][2], aFl[0][3], base + AL_OFF + offA0);
        ldsm_x4(aFl[1][0], aFl[1][1], aFl[1][2], aFl[1][3], base + AL_OFF + offA1);
#pragma unroll
        for (int mf = 0; mf < 2; mf++)
#pragma unroll
            for (int nf = 0; nf < 4; nf++) mma16816(acc[mf][nf], aFl[mf], bFh[nf]);
    };

    // prologue: 3 stages in flight
    issue(0, stage0);
    issue(1, stage1);
    issue(2, stage2);

    const uint32_t stages[4] = {stage0, stage1, stage2, stage3};
    for (int ch4 = 0; ch4 < NCH; ch4 += 4) {
#pragma unroll
        for (int u = 0; u < 4; u++) {
            CP_WAIT2();
            __syncthreads();
            mma_ks(stages[u], ch4 + u + 3, stages[(u + 3) & 3]);
        }
    }
    CP_WAIT0();
    __syncthreads();

    // ---- epilogue: stage accums -> smem [128][68] -> coalesced writes ----
    float* eps = reinterpret_cast<float*>(smem);
    const int g = lane >> 2, c = lane & 3;
#pragma unroll
    for (int mf = 0; mf < 2; mf++)
#pragma unroll
        for (int nf = 0; nf < 4; nf++) {
            int r  = m0w + mf * 16 + g;
            int cc = n0w + nf * 8 + 2 * c;
            *reinterpret_cast<float2*>(&eps[r * 68 + cc]) =
                make_float2(acc[mf][nf][0], acc[mf][nf][1]);
            *reinterpret_cast<float2*>(&eps[(r + 8) * 68 + cc]) =
                make_float2(acc[mf][nf][2], acc[mf][nf][3]);
        }
    __syncthreads();

    if (Chi) {
        __nv_bfloat16* ph = Chi + (size_t)blockIdx.z * strC;
        __nv_bfloat16* pl = Clo + (size_t)blockIdx.z * strC;
#pragma unroll
        for (int it = 0; it < 8; it++) {
            int idx = tid + it * 256;
            int row = idx >> 4;
            int c4  = (idx & 15) << 2;
            float4 v = *reinterpret_cast<float4*>(&eps[row * 68 + c4]);
            float4 bz = *reinterpret_cast<const float4*>(&bias[col0 + c4]);
            v.x += bz.x; v.y += bz.y; v.z += bz.z; v.w += bz.w;
            uint2 hi, lo;
            split2(v, hi, lo);
            size_t o = (size_t)(row0 + row) * N + col0 + c4;
            *reinterpret_cast<uint2*>(&ph[o]) = hi;
            *reinterpret_cast<uint2*>(&pl[o]) = lo;
        }
    } else {
        float* Cb = C + (size_t)blockIdx.z * strC;
#pragma unroll
        for (int it = 0; it < 8; it++) {
            int idx = tid + it * 256;
            int row = idx >> 4;
            int c4  = (idx & 15) << 2;
            float4 v = *reinterpret_cast<float4*>(&eps[row * 68 + c4]);
            *reinterpret_cast<float4*>(&Cb[(size_t)(row0 + row) * N + col0 + c4]) = v;
        }
    }
}

// ============================================================
// prep_x: X -> X_hi/X_lo + XT_hi/XT_lo
// ============================================================
__global__ __launch_bounds__(256) void prep_x(
    const float* __restrict__ X,
    __nv_bfloat16* __restrict__ Xhi, __nv_bfloat16* __restrict__ Xlo,
    __nv_bfloat16* __restrict__ XThi, __nv_bfloat16* __restrict__ XTlo)
{
    __shared__ float t[32][33];
    const int b = blockIdx.z;
    const int s0 = blockIdx.x * 32, d0 = blockIdx.y * 32;
    const size_t bo = (size_t)b * SS * DD;
    const int tx = threadIdx.x, ty = threadIdx.y;
#pragma unroll
    for (int j = 0; j < 4; j++) {
        int s = s0 + ty + 8 * j;
        float v = X[bo + (size_t)s * DD + d0 + tx];
        t[ty + 8 * j][tx] = v;
        __nv_bfloat16 h = __float2bfloat16(v);
        Xhi[bo + (size_t)s * DD + d0 + tx] = h;
        Xlo[bo + (size_t)s * DD + d0 + tx] = __float2bfloat16(v - __bfloat162float(h));
    }
    __syncthreads();
#pragma unroll
    for (int j = 0; j < 4; j++) {
        int d = d0 + ty + 8 * j;
        float v = t[tx][ty + 8 * j];
        __nv_bfloat16 h = __float2bfloat16(v);
        XThi[bo + (size_t)d * SS + s0 + tx] = h;
        XTlo[bo + (size_t)d * SS + s0 + tx] = __float2bfloat16(v - __bfloat162float(h));
    }
}

__global__ __launch_bounds__(256) void split_w(
    const float* __restrict__ W,
    __nv_bfloat16* __restrict__ Whi, __nv_bfloat16* __restrict__ Wlo)
{
    int idx = blockIdx.x * 256 + threadIdx.x;
    float4 v = reinterpret_cast<const float4*>(W)[idx];
    uint2 hi, lo;
    split2(v, hi, lo);
    reinterpret_cast<uint2*>(Whi)[idx] = hi;
    reinterpret_cast<uint2*>(Wlo)[idx] = lo;
}

// ============================================================
// In-place row softmax + split bf16 out
// ============================================================
__device__ __forceinline__ float warp_max(float v) {
#pragma unroll
    for (int o = 16; o > 0; o >>= 1) v = fmaxf(v, __shfl_xor_sync(0xFFFFFFFFu, v, o));
    return v;
}
__device__ __forceinline__ float warp_sum(float v) {
#pragma unroll
    for (int o = 16; o > 0; o >>= 1) v += __shfl_xor_sync(0xFFFFFFFFu, v, o);
    return v;
}

__global__ __launch_bounds__(256) void softmax_rows(
    float* __restrict__ attn,
    __nv_bfloat16* __restrict__ Ahi, __nv_bfloat16* __restrict__ Alo)
{
    __shared__ float red[8];
    const size_t ro = (size_t)blockIdx.x * SS;
    float* row = attn + ro;
    const int tid = threadIdx.x, lane = tid & 31, wid = tid >> 5;

    float4 v[2];
    v[0] = *reinterpret_cast<const float4*>(&row[tid * 4]);
    v[1] = *reinterpret_cast<const float4*>(&row[(tid + 256) * 4]);

    float mx = -INFINITY;
#pragma unroll
    for (int i = 0; i < 2; i++)
        mx = fmaxf(mx, fmaxf(fmaxf(v[i].x, v[i].y), fmaxf(v[i].z, v[i].w)));
    mx = warp_max(mx);
    if (lane == 0) red[wid] = mx;
    __syncthreads();
    if (wid == 0) {
        float t = (lane < 8) ? red[lane] : -INFINITY;
        t = warp_max(t);
        if (lane == 0) red[0] = t;
    }
    __syncthreads();
    mx = red[0];
    __syncthreads();

    float s = 0.f;
#pragma unroll
    for (int i = 0; i < 2; i++) {
        v[i].x = expf(v[i].x - mx); s += v[i].x;
        v[i].y = expf(v[i].y - mx); s += v[i].y;
        v[i].z = expf(v[i].z - mx); s += v[i].z;
        v[i].w = expf(v[i].w - mx); s += v[i].w;
    }
    s = warp_sum(s);
    if (lane == 0) red[wid] = s;
    __syncthreads();
    if (wid == 0) {
        float t = (lane < 8) ? red[lane] : 0.0f;
        t = warp_sum(t);
        if (lane == 0) red[0] = t;
    }
    __syncthreads();
    float inv = 1.0f / red[0];

#pragma unroll
    for (int i = 0; i < 2; i++) { v[i].x *= inv; v[i].y *= inv; v[i].z *= inv; v[i].w *= inv; }
    *reinterpret_cast<float4*>(&row[tid * 4])         = v[0];
    *reinterpret_cast<float4*>(&row[(tid + 256) * 4]) = v[1];

    uint2 hi, lo;
    split2(v[0], hi, lo);
    *reinterpret_cast<uint2*>(&Ahi[ro + tid * 4]) = hi;
    *reinterpret_cast<uint2*>(&Alo[ro + tid * 4]) = lo;
    split2(v[1], hi, lo);
    *reinterpret_cast<uint2*>(&Ahi[ro + (tid + 256) * 4]) = hi;
    *reinterpret_cast<uint2*>(&Alo[ro + (tid + 256) * 4]) = lo;
}

// ============================================================
// kernel_launch
// ============================================================
extern "C" void kernel_launch(void* const* d_in, const int* in_sizes, int n_in,
                              void* d_out, int out_size)
{
    const float* X    = (const float*)d_in[0];
    const float* W    = (const float*)d_in[1];
    const float* bias = (const float*)d_in[2];

    float* ctx  = (float*)d_out;                           // [8,2048,1024]
    float* attn = (float*)d_out + (size_t)BB * SS * DD;    // [8,2048,2048]

    __nv_bfloat16 *xhi, *xlo, *xthi, *xtlo, *whi, *wlo, *phi, *plo, *ahi, *alo;
    cudaGetSymbolAddress((void**)&xhi,  g_xhi);
    cudaGetSymbolAddress((void**)&xlo,  g_xlo);
    cudaGetSymbolAddress((void**)&xthi, g_xthi);
    cudaGetSymbolAddress((void**)&xtlo, g_xtlo);
    cudaGetSymbolAddress((void**)&whi,  g_whi);
    cudaGetSymbolAddress((void**)&wlo,  g_wlo);
    cudaGetSymbolAddress((void**)&phi,  g_phi);
    cudaGetSymbolAddress((void**)&plo,  g_plo);
    cudaGetSymbolAddress((void**)&ahi,  g_ahi);
    cudaGetSymbolAddress((void**)&alo,  g_alo);

    cudaFuncSetAttribute(gemm_nt_mma, cudaFuncAttributeMaxDynamicSharedMemorySize, GEMM_SMEM);

    const long long sXD = (long long)SS * DD;
    const long long sAA = (long long)SS * SS;

    {
        dim3 grid(SS / 32, DD / 32, BB);
        prep_x<<<grid, dim3(32, 8)>>>(X, xhi, xlo, xthi, xtlo);
    }
    split_w<<<(DD * DD / 4) / 256, 256>>>(W, whi, wlo);

    // GEMM1: proj = X * W^T + b  -> split bf16 pair
    {
        dim3 grid(DD / 64, (BB * SS) / 128, 1);
        gemm_nt_mma<<<grid, 256, GEMM_SMEM>>>(xhi, xlo, whi, wlo,
                                              nullptr, phi, plo, bias,
                                              BB * SS, DD, DD, 0, 0, 0);
    }
    // GEMM2: attn[b] = X[b] * proj[b]^T  (fp32 out)
    {
        dim3 grid(SS / 64, SS / 128, BB);
        gemm_nt_mma<<<grid, 256, GEMM_SMEM>>>(xhi, xlo, phi, plo,
                                              attn, nullptr, nullptr, nullptr,
                                              SS, SS, DD, sXD, sXD, sAA);
    }
    softmax_rows<<<BB * SS, 256>>>(attn, ahi, alo);
    // GEMM3: ctx[b] = attn[b] * XT[b]^T  (fp32 out)
    {
        dim3 grid(DD / 64, SS / 128, BB);
        gemm_nt_mma<<<grid, 256, GEMM_SMEM>>>(ahi, alo, xthi, xtlo,
                                              ctx, nullptr, nullptr, nullptr,
                                              SS, DD, SS, sAA, sXD, sXD);
    }
}

// round 16
// speedup vs baseline: 1.6765x; 1.0217x over previous
#include <cuda_runtime.h>
#include <cuda_bf16.h>
#include <math.h>
#include <stdint.h>

// Problem shape (fixed by the dataset)
#define BB 8
#define SS 2048
#define DD 1024

// Pre-split bf16 operand arrays (device globals — allocation-guard-safe)
__device__ __nv_bfloat16 g_xhi[(size_t)BB * SS * DD];
__device__ __nv_bfloat16 g_xlo[(size_t)BB * SS * DD];
__device__ __nv_bfloat16 g_xthi[(size_t)BB * SS * DD];
__device__ __nv_bfloat16 g_xtlo[(size_t)BB * SS * DD];
__device__ __nv_bfloat16 g_whi[(size_t)DD * DD];
__device__ __nv_bfloat16 g_wlo[(size_t)DD * DD];
__device__ __nv_bfloat16 g_phi[(size_t)BB * SS * DD];
__device__ __nv_bfloat16 g_plo[(size_t)BB * SS * DD];
__device__ __nv_bfloat16 g_ahi[(size_t)BB * SS * SS];
__device__ __nv_bfloat16 g_alo[(size_t)BB * SS * SS];

// ============================================================
// R16 = R13 locked in (best measured config, 1336.5 us):
// 128x64 CTA tile, BK=16, 4-stage ring, one barrier/chunk, 3 CTAs/SM,
// 32x32 warp tiles, all hot-loop ALU hoisted, compile-time x4 unroll,
// all 8 LDSM front-loaded per chunk (R15 proved deferral is negative).
// fp32 via pre-split bf16 hi/lo operands, 3 tensor products (hh, hl, lh).
// Converged at the mma.sync shared-memory-port floor (~97% port busy
// at tensor=69%); tcgen05 unavailable under this toolchain's PTX target.
// ============================================================

#define AH_OFF 0
#define AL_OFF 4096
#define BH_OFF 8192
#define BL_OFF 10240
#define STAGE_B 12288
#define GEMM_SMEM (4 * STAGE_B)   // 48 KB (>= epilogue's 34.8 KB)

__device__ __forceinline__ uint32_t smem_u32(const void* p) {
    uint32_t a;
    asm("{ .reg .u64 t; cvta.to.shared.u64 t, %1; cvt.u32.u64 %0, t; }" : "=r"(a) : "l"(p));
    return a;
}
__device__ __forceinline__ uint32_t sw32(uint32_t off) {
    return off ^ ((off >> 3) & 0x10);
}
__device__ __forceinline__ void ldsm_x4(uint32_t& r0, uint32_t& r1, uint32_t& r2, uint32_t& r3,
                                        uint32_t addr) {
    asm volatile("ldmatrix.sync.aligned.m8n8.x4.shared.b16 {%0,%1,%2,%3}, [%4];"
                 : "=r"(r0), "=r"(r1), "=r"(r2), "=r"(r3) : "r"(addr));
}
__device__ __forceinline__ void mma16816(float* d, const uint32_t* a, const uint32_t* b) {
    asm volatile(
        "mma.sync.aligned.m16n8k16.row.col.f32.bf16.bf16.f32 "
        "{%0,%1,%2,%3}, {%4,%5,%6,%7}, {%8,%9}, {%0,%1,%2,%3};"
        : "+f"(d[0]), "+f"(d[1]), "+f"(d[2]), "+f"(d[3])
        : "r"(a[0]), "r"(a[1]), "r"(a[2]), "r"(a[3]), "r"(b[0]), "r"(b[1]));
}

#define CP_ASYNC16(dst, src) \
    asm volatile("cp.async.cg.shared.global [%0], [%1], 16;" :: "r"(dst), "l"(src) : "memory")
#define CP_COMMIT()  asm volatile("cp.async.commit_group;" ::: "memory")
#define CP_WAIT2()   asm volatile("cp.async.wait_group 2;" ::: "memory")
#define CP_WAIT0()   asm volatile("cp.async.wait_group 0;" ::: "memory")

__device__ __forceinline__ void split2(const float4& v, uint2& hi, uint2& lo) {
    __nv_bfloat162 h0 = __floats2bfloat162_rn(v.x, v.y);
    __nv_bfloat162 h1 = __floats2bfloat162_rn(v.z, v.w);
    float r0 = v.x - __bfloat162float(__low2bfloat16(h0));
    float r1 = v.y - __bfloat162float(__high2bfloat16(h0));
    float r2 = v.z - __bfloat162float(__low2bfloat16(h1));
    float r3 = v.w - __bfloat162float(__high2bfloat16(h1));
    __nv_bfloat162 l0 = __floats2bfloat162_rn(r0, r1);
    __nv_bfloat162 l1 = __floats2bfloat162_rn(r2, r3);
    hi.x = *reinterpret_cast<uint32_t*>(&h0);
    hi.y = *reinterpret_cast<uint32_t*>(&h1);
    lo.x = *reinterpret_cast<uint32_t*>(&l0);
    lo.y = *reinterpret_cast<uint32_t*>(&l1);
}

__global__ __launch_bounds__(256, 3) void gemm_nt_mma(
    const __nv_bfloat16* __restrict__ Ahi, const __nv_bfloat16* __restrict__ Alo,
    const __nv_bfloat16* __restrict__ Bhi, const __nv_bfloat16* __restrict__ Blo,
    float* __restrict__ C, __nv_bfloat16* __restrict__ Chi, __nv_bfloat16* __restrict__ Clo,
    const float* __restrict__ bias,
    int M, int N, int K,
    long long strA, long long strB, long long strC)
{
    extern __shared__ __align__(1024) char smem[];
    const uint32_t sb = smem_u32(smem);
    const int tid = threadIdx.x, wid = tid >> 5, lane = tid & 31;
    const int row0 = blockIdx.y * 128, col0 = blockIdx.x * 64;

    Ahi += (size_t)blockIdx.z * strA;  Alo += (size_t)blockIdx.z * strA;
    Bhi += (size_t)blockIdx.z * strB;  Blo += (size_t)blockIdx.z * strB;

    // 4m x 2n warp grid, 32x32 warp tiles
    const int wm = wid & 3, wn = wid >> 2;
    const int m0w = wm * 32, n0w = wn * 32;

    // ---- cp.async loader indexing (BK=16 -> 32B rows) ----
    const int la_row = tid >> 1;
    const int la_s   = tid & 1;
    const int lb_row = (tid & 127) >> 1;
    const int lb_s   = tid & 1;
    const bool do_b  = (tid < 128);

    // Hoisted: global pointers as u64 (cvta once)
    const unsigned long long pah = (unsigned long long)__cvta_generic_to_global(
        (const void*)(Ahi + (size_t)(row0 + la_row) * K + la_s * 8));
    const unsigned long long pal = (unsigned long long)__cvta_generic_to_global(
        (const void*)(Alo + (size_t)(row0 + la_row) * K + la_s * 8));
    const unsigned long long pbh = (unsigned long long)__cvta_generic_to_global(
        (const void*)(Bhi + (size_t)(col0 + lb_row) * K + lb_s * 8));
    const unsigned long long pbl = (unsigned long long)__cvta_generic_to_global(
        (const void*)(Blo + (size_t)(col0 + lb_row) * K + lb_s * 8));

    // Hoisted: swizzled store offsets
    const uint32_t swa = sw32((uint32_t)(la_row * 32 + la_s * 16));
    const uint32_t swb = sw32((uint32_t)(lb_row * 32 + lb_s * 16));

    // Hoisted: ldmatrix swizzled offsets (loop-invariant)
    const uint32_t a_lrow = (uint32_t)(lane & 15);
    const uint32_t a_lc16 = (uint32_t)(lane >> 4) * 16;
    const uint32_t b_lrow = (uint32_t)((lane & 7) + ((lane >> 4) & 1) * 8);
    const uint32_t b_lk16 = (uint32_t)((lane >> 3) & 1) * 16;
    const uint32_t offA0 = sw32((uint32_t)((m0w + a_lrow) * 32 + a_lc16));
    const uint32_t offA1 = sw32((uint32_t)((m0w + 16 + a_lrow) * 32 + a_lc16));
    const uint32_t offB0 = sw32((uint32_t)((n0w + b_lrow) * 32 + b_lk16));
    const uint32_t offB1 = sw32((uint32_t)((n0w + 16 + b_lrow) * 32 + b_lk16));

    // Hoisted: stage base addresses
    const uint32_t stage0 = sb;
    const uint32_t stage1 = sb + STAGE_B;
    const uint32_t stage2 = sb + 2 * STAGE_B;
    const uint32_t stage3 = sb + 3 * STAGE_B;

    float acc[2][4][4];
#pragma unroll
    for (int i = 0; i < 2; i++)
#pragma unroll
        for (int j = 0; j < 4; j++)
#pragma unroll
            for (int q = 0; q < 4; q++) acc[i][j][q] = 0.f;

    const int NCH = K >> 4;   // BK=16; 64 or 128 here (divisible by 4)

    auto issue = [&](int ch, uint32_t st) {
        if (ch < NCH) {
            const unsigned long long koff = (unsigned long long)(ch << 5);  // bytes
            CP_ASYNC16(st + AH_OFF + swa, pah + koff);
            CP_ASYNC16(st + AL_OFF + swa, pal + koff);
            if (do_b) {
                CP_ASYNC16(st + BH_OFF + swb, pbh + koff);
                CP_ASYNC16(st + BL_OFF + swb, pbl + koff);
            }
        }
        CP_COMMIT();
    };

    // One chunk (k16): 8 LDSM.x4 front-loaded -> 24 MMAs in 3 bursts of 8.
    auto mma_ks = [&](uint32_t base) {
        uint32_t aFh[2][4], bFh[4][2], bFl[4][2];
        ldsm_x4(aFh[0][0], aFh[0][1], aFh[0][2], aFh[0][3], base + AH_OFF + offA0);
        ldsm_x4(aFh[1][0], aFh[1][1], aFh[1][2], aFh[1][3], base + AH_OFF + offA1);
        {
            uint32_t r0, r1, r2, r3;
            ldsm_x4(r0, r1, r2, r3, base + BH_OFF + offB0);
            bFh[0][0] = r0; bFh[0][1] = r1; bFh[1][0] = r2; bFh[1][1] = r3;
            ldsm_x4(r0, r1, r2, r3, base + BH_OFF + offB1);
            bFh[2][0] = r0; bFh[2][1] = r1; bFh[3][0] = r2; bFh[3][1] = r3;
            ldsm_x4(r0, r1, r2, r3, base + BL_OFF + offB0);
            bFl[0][0] = r0; bFl[0][1] = r1; bFl[1][0] = r2; bFl[1][1] = r3;
            ldsm_x4(r0, r1, r2, r3, base + BL_OFF + offB1);
            bFl[2][0] = r0; bFl[2][1] = r1; bFl[3][0] = r2; bFl[3][1] = r3;
        }
        // burst 1: hh
#pragma unroll
        for (int mf = 0; mf < 2; mf++)
#pragma unroll
            for (int nf = 0; nf < 4; nf++) mma16816(acc[mf][nf], aFh[mf], bFh[nf]);
        // burst 2: hi(A) * lo(B)
#pragma unroll
        for (int mf = 0; mf < 2; mf++)
#pragma unroll
            for (int nf = 0; nf < 4; nf++) mma16816(acc[mf][nf], aFh[mf], bFl[nf]);
        // burst 3: lo(A) * hi(B)
        uint32_t aFl[2][4];
        ldsm_x4(aFl[0][0], aFl[0][1], aFl[0][2], aFl[0][3], base + AL_OFF + offA0);
        ldsm_x4(aFl[1][0], aFl[1][1], aFl[1][2], aFl[1][3], base + AL_OFF + offA1);
#pragma unroll
        for (int mf = 0; mf < 2; mf++)
#pragma unroll
            for (int nf = 0; nf < 4; nf++) mma16816(acc[mf][nf], aFl[mf], bFh[nf]);
    };

    // prologue: 3 stages in flight
    issue(0, stage0);
    issue(1, stage1);
    issue(2, stage2);

    const uint32_t stages[4] = {stage0, stage1, stage2, stage3};
    for (int ch4 = 0; ch4 < NCH; ch4 += 4) {
#pragma unroll
        for (int u = 0; u < 4; u++) {
            CP_WAIT2();
            __syncthreads();
            issue(ch4 + u + 3, stages[(u + 3) & 3]);
            mma_ks(stages[u]);
        }
    }
    CP_WAIT0();
    __syncthreads();

    // ---- epilogue: stage accums -> smem [128][68] -> coalesced writes ----
    float* eps = reinterpret_cast<float*>(smem);
    const int g = lane >> 2, c = lane & 3;
#pragma unroll
    for (int mf = 0; mf < 2; mf++)
#pragma unroll
        for (int nf = 0; nf < 4; nf++) {
            int r  = m0w + mf * 16 + g;
            int cc = n0w + nf * 8 + 2 * c;
            *reinterpret_cast<float2*>(&eps[r * 68 + cc]) =
                make_float2(acc[mf][nf][0], acc[mf][nf][1]);
            *reinterpret_cast<float2*>(&eps[(r + 8) * 68 + cc]) =
                make_float2(acc[mf][nf][2], acc[mf][nf][3]);
        }
    __syncthreads();

    if (Chi) {
        __nv_bfloat16* ph = Chi + (size_t)blockIdx.z * strC;
        __nv_bfloat16* pl = Clo + (size_t)blockIdx.z * strC;
#pragma unroll
        for (int it = 0; it < 8; it++) {
            int idx = tid + it * 256;
            int row = idx >> 4;
            int c4  = (idx & 15) << 2;
            float4 v = *reinterpret_cast<float4*>(&eps[row * 68 + c4]);
            float4 bz = *reinterpret_cast<const float4*>(&bias[col0 + c4]);
            v.x += bz.x; v.y += bz.y; v.z += bz.z; v.w += bz.w;
            uint2 hi, lo;
            split2(v, hi, lo);
            size_t o = (size_t)(row0 + row) * N + col0 + c4;
            *reinterpret_cast<uint2*>(&ph[o]) = hi;
            *reinterpret_cast<uint2*>(&pl[o]) = lo;
        }
    } else {
        float* Cb = C + (size_t)blockIdx.z * strC;
#pragma unroll
        for (int it = 0; it < 8; it++) {
            int idx = tid + it * 256;
            int row = idx >> 4;
            int c4  = (idx & 15) << 2;
            float4 v = *reinterpret_cast<float4*>(&eps[row * 68 + c4]);
            *reinterpret_cast<float4*>(&Cb[(size_t)(row0 + row) * N + col0 + c4]) = v;
        }
    }
}

// ============================================================
// prep_x: X -> X_hi/X_lo + XT_hi/XT_lo
// ============================================================
__global__ __launch_bounds__(256) void prep_x(
    const float* __restrict__ X,
    __nv_bfloat16* __restrict__ Xhi, __nv_bfloat16* __restrict__ Xlo,
    __nv_bfloat16* __restrict__ XThi, __nv_bfloat16* __restrict__ XTlo)
{
    __shared__ float t[32][33];
    const int b = blockIdx.z;
    const int s0 = blockIdx.x * 32, d0 = blockIdx.y * 32;
    const size_t bo = (size_t)b * SS * DD;
    const int tx = threadIdx.x, ty = threadIdx.y;
#pragma unroll
    for (int j = 0; j < 4; j++) {
        int s = s0 + ty + 8 * j;
        float v = X[bo + (size_t)s * DD + d0 + tx];
        t[ty + 8 * j][tx] = v;
        __nv_bfloat16 h = __float2bfloat16(v);
        Xhi[bo + (size_t)s * DD + d0 + tx] = h;
        Xlo[bo + (size_t)s * DD + d0 + tx] = __float2bfloat16(v - __bfloat162float(h));
    }
    __syncthreads();
#pragma unroll
    for (int j = 0; j < 4; j++) {
        int d = d0 + ty + 8 * j;
        float v = t[tx][ty + 8 * j];
        __nv_bfloat16 h = __float2bfloat16(v);
        XThi[bo + (size_t)d * SS + s0 + tx] = h;
        XTlo[bo + (size_t)d * SS + s0 + tx] = __float2bfloat16(v - __bfloat162float(h));
    }
}

__global__ __launch_bounds__(256) void split_w(
    const float* __restrict__ W,
    __nv_bfloat16* __restrict__ Whi, __nv_bfloat16* __restrict__ Wlo)
{
    int idx = blockIdx.x * 256 + threadIdx.x;
    float4 v = reinterpret_cast<const float4*>(W)[idx];
    uint2 hi, lo;
    split2(v, hi, lo);
    reinterpret_cast<uint2*>(Whi)[idx] = hi;
    reinterpret_cast<uint2*>(Wlo)[idx] = lo;
}

// ============================================================
// In-place row softmax + split bf16 out
// ============================================================
__device__ __forceinline__ float warp_max(float v) {
#pragma unroll
    for (int o = 16; o > 0; o >>= 1) v = fmaxf(v, __shfl_xor_sync(0xFFFFFFFFu, v, o));
    return v;
}
__device__ __forceinline__ float warp_sum(float v) {
#pragma unroll
    for (int o = 16; o > 0; o >>= 1) v += __shfl_xor_sync(0xFFFFFFFFu, v, o);
    return v;
}

__global__ __launch_bounds__(256) void softmax_rows(
    float* __restrict__ attn,
    __nv_bfloat16* __restrict__ Ahi, __nv_bfloat16* __restrict__ Alo)
{
    __shared__ float red[8];
    const size_t ro = (size_t)blockIdx.x * SS;
    float* row = attn + ro;
    const int tid = threadIdx.x, lane = tid & 31, wid = tid >> 5;

    float4 v[2];
    v[0] = *reinterpret_cast<const float4*>(&row[tid * 4]);
    v[1] = *reinterpret_cast<const float4*>(&row[(tid + 256) * 4]);

    float mx = -INFINITY;
#pragma unroll
    for (int i = 0; i < 2; i++)
        mx = fmaxf(mx, fmaxf(fmaxf(v[i].x, v[i].y), fmaxf(v[i].z, v[i].w)));
    mx = warp_max(mx);
    if (lane == 0) red[wid] = mx;
    __syncthreads();
    if (wid == 0) {
        float t = (lane < 8) ? red[lane] : -INFINITY;
        t = warp_max(t);
        if (lane == 0) red[0] = t;
    }
    __syncthreads();
    mx = red[0];
    __syncthreads();

    float s = 0.f;
#pragma unroll
    for (int i = 0; i < 2; i++) {
        v[i].x = expf(v[i].x - mx); s += v[i].x;
        v[i].y = expf(v[i].y - mx); s += v[i].y;
        v[i].z = expf(v[i].z - mx); s += v[i].z;
        v[i].w = expf(v[i].w - mx); s += v[i].w;
    }
    s = warp_sum(s);
    if (lane == 0) red[wid] = s;
    __syncthreads();
    if (wid == 0) {
        float t = (lane < 8) ? red[lane] : 0.0f;
        t = warp_sum(t);
        if (lane == 0) red[0] = t;
    }
    __syncthreads();
    float inv = 1.0f / red[0];

#pragma unroll
    for (int i = 0; i < 2; i++) { v[i].x *= inv; v[i].y *= inv; v[i].z *= inv; v[i].w *= inv; }
    *reinterpret_cast<float4*>(&row[tid * 4])         = v[0];
    *reinterpret_cast<float4*>(&row[(tid + 256) * 4]) = v[1];

    uint2 hi, lo;
    split2(v[0], hi, lo);
    *reinterpret_cast<uint2*>(&Ahi[ro + tid * 4]) = hi;
    *reinterpret_cast<uint2*>(&Alo[ro + tid * 4]) = lo;
    split2(v[1], hi, lo);
    *reinterpret_cast<uint2*>(&Ahi[ro + (tid + 256) * 4]) = hi;
    *reinterpret_cast<uint2*>(&Alo[ro + (tid + 256) * 4]) = lo;
}

// ============================================================
// kernel_launch
// ============================================================
extern "C" void kernel_launch(void* const* d_in, const int* in_sizes, int n_in,
                              void* d_out, int out_size)
{
    const float* X    = (const float*)d_in[0];
    const float* W    = (const float*)d_in[1];
    const float* bias = (const float*)d_in[2];

    float* ctx  = (float*)d_out;                           // [8,2048,1024]
    float* attn = (float*)d_out + (size_t)BB * SS * DD;    // [8,2048,2048]

    __nv_bfloat16 *xhi, *xlo, *xthi, *xtlo, *whi, *wlo, *phi, *plo, *ahi, *alo;
    cudaGetSymbolAddress((void**)&xhi,  g_xhi);
    cudaGetSymbolAddress((void**)&xlo,  g_xlo);
    cudaGetSymbolAddress((void**)&xthi, g_xthi);
    cudaGetSymbolAddress((void**)&xtlo, g_xtlo);
    cudaGetSymbolAddress((void**)&whi,  g_whi);
    cudaGetSymbolAddress((void**)&wlo,  g_wlo);
    cudaGetSymbolAddress((void**)&phi,  g_phi);
    cudaGetSymbolAddress((void**)&plo,  g_plo);
    cudaGetSymbolAddress((void**)&ahi,  g_ahi);
    cudaGetSymbolAddress((void**)&alo,  g_alo);

    cudaFuncSetAttribute(gemm_nt_mma, cudaFuncAttributeMaxDynamicSharedMemorySize, GEMM_SMEM);

    const long long sXD = (long long)SS * DD;
    const long long sAA = (long long)SS * SS;

    {
        dim3 grid(SS / 32, DD / 32, BB);
        prep_x<<<grid, dim3(32, 8)>>>(X, xhi, xlo, xthi, xtlo);
    }
    split_w<<<(DD * DD / 4) / 256, 256>>>(W, whi, wlo);

    // GEMM1: proj = X * W^T + b  -> split bf16 pair
    {
        dim3 grid(DD / 64, (BB * SS) / 128, 1);
        gemm_nt_mma<<<grid, 256, GEMM_SMEM>>>(xhi, xlo, whi, wlo,
                                              nullptr, phi, plo, bias,
                                              BB * SS, DD, DD, 0, 0, 0);
    }
    // GEMM2: attn[b] = X[b] * proj[b]^T  (fp32 out)
    {
        dim3 grid(SS / 64, SS / 128, BB);
        gemm_nt_mma<<<grid, 256, GEMM_SMEM>>>(xhi, xlo, phi, plo,
                                              attn, nullptr, nullptr, nullptr,
                                              SS, SS, DD, sXD, sXD, sAA);
    }
    softmax_rows<<<BB * SS, 256>>>(attn, ahi, alo);
    // GEMM3: ctx[b] = attn[b] * XT[b]^T  (fp32 out)
    {
        dim3 grid(DD / 64, SS / 128, BB);
        gemm_nt_mma<<<grid, 256, GEMM_SMEM>>>(ahi, alo, xthi, xtlo,
                                              ctx, nullptr, nullptr, nullptr,
                                              SS, DD, SS, sAA, sXD, sXD);
    }
}

// round 17
// speedup vs baseline: 1.6776x; 1.0007x over previous
#include <cuda_runtime.h>
#include <cuda_bf16.h>
#include <math.h>
#include <stdint.h>

// Problem shape (fixed by the dataset)
#define BB 8
#define SS 2048
#define DD 1024

// Pre-split bf16 operand arrays (device globals — allocation-guard-safe)
__device__ __nv_bfloat16 g_xhi[(size_t)BB * SS * DD];
__device__ __nv_bfloat16 g_xlo[(size_t)BB * SS * DD];
__device__ __nv_bfloat16 g_xthi[(size_t)BB * SS * DD];
__device__ __nv_bfloat16 g_xtlo[(size_t)BB * SS * DD];
__device__ __nv_bfloat16 g_whi[(size_t)DD * DD];
__device__ __nv_bfloat16 g_wlo[(size_t)DD * DD];
__device__ __nv_bfloat16 g_phi[(size_t)BB * SS * DD];
__device__ __nv_bfloat16 g_plo[(size_t)BB * SS * DD];
__device__ __nv_bfloat16 g_ahi[(size_t)BB * SS * SS];
__device__ __nv_bfloat16 g_alo[(size_t)BB * SS * SS];

// ============================================================
// R17 = R13/R16 GEMM core (converged: 128x64 CTA tile, BK=16, 4-stage
// ring, one barrier/chunk, 3 CTAs/SM, 32x32 warp tiles, hoisted ALU,
// compile-time x4 unroll, front-loaded LDSM) + VECTORIZED prep_x
// (float4 loads, uint2 stores, pad-33 conflict-free transpose).
// ============================================================

#define AH_OFF 0
#define AL_OFF 4096
#define BH_OFF 8192
#define BL_OFF 10240
#define STAGE_B 12288
#define GEMM_SMEM (4 * STAGE_B)   // 48 KB (>= epilogue's 34.8 KB)

__device__ __forceinline__ uint32_t smem_u32(const void* p) {
    uint32_t a;
    asm("{ .reg .u64 t; cvta.to.shared.u64 t, %1; cvt.u32.u64 %0, t; }" : "=r"(a) : "l"(p));
    return a;
}
__device__ __forceinline__ uint32_t sw32(uint32_t off) {
    return off ^ ((off >> 3) & 0x10);
}
__device__ __forceinline__ void ldsm_x4(uint32_t& r0, uint32_t& r1, uint32_t& r2, uint32_t& r3,
                                        uint32_t addr) {
    asm volatile("ldmatrix.sync.aligned.m8n8.x4.shared.b16 {%0,%1,%2,%3}, [%4];"
                 : "=r"(r0), "=r"(r1), "=r"(r2), "=r"(r3) : "r"(addr));
}
__device__ __forceinline__ void mma16816(float* d, const uint32_t* a, const uint32_t* b) {
    asm volatile(
        "mma.sync.aligned.m16n8k16.row.col.f32.bf16.bf16.f32 "
        "{%0,%1,%2,%3}, {%4,%5,%6,%7}, {%8,%9}, {%0,%1,%2,%3};"
        : "+f"(d[0]), "+f"(d[1]), "+f"(d[2]), "+f"(d[3])
        : "r"(a[0]), "r"(a[1]), "r"(a[2]), "r"(a[3]), "r"(b[0]), "r"(b[1]));
}

#define CP_ASYNC16(dst, src) \
    asm volatile("cp.async.cg.shared.global [%0], [%1], 16;" :: "r"(dst), "l"(src) : "memory")
#define CP_COMMIT()  asm volatile("cp.async.commit_group;" ::: "memory")
#define CP_WAIT2()   asm volatile("cp.async.wait_group 2;" ::: "memory")
#define CP_WAIT0()   asm volatile("cp.async.wait_group 0;" ::: "memory")

__device__ __forceinline__ void split2(const float4& v, uint2& hi, uint2& lo) {
    __nv_bfloat162 h0 = __floats2bfloat162_rn(v.x, v.y);
    __nv_bfloat162 h1 = __floats2bfloat162_rn(v.z, v.w);
    float r0 = v.x - __bfloat162float(__low2bfloat16(h0));
    float r1 = v.y - __bfloat162float(__high2bfloat16(h0));
    float r2 = v.z - __bfloat162float(__low2bfloat16(h1));
    float r3 = v.w - __bfloat162float(__high2bfloat16(h1));
    __nv_bfloat162 l0 = __floats2bfloat162_rn(r0, r1);
    __nv_bfloat162 l1 = __floats2bfloat162_rn(r2, r3);
    hi.x = *reinterpret_cast<uint32_t*>(&h0);
    hi.y = *reinterpret_cast<uint32_t*>(&h1);
    lo.x = *reinterpret_cast<uint32_t*>(&l0);
    lo.y = *reinterpret_cast<uint32_t*>(&l1);
}

__global__ __launch_bounds__(256, 3) void gemm_nt_mma(
    const __nv_bfloat16* __restrict__ Ahi, const __nv_bfloat16* __restrict__ Alo,
    const __nv_bfloat16* __restrict__ Bhi, const __nv_bfloat16* __restrict__ Blo,
    float* __restrict__ C, __nv_bfloat16* __restrict__ Chi, __nv_bfloat16* __restrict__ Clo,
    const float* __restrict__ bias,
    int M, int N, int K,
    long long strA, long long strB, long long strC)
{
    extern __shared__ __align__(1024) char smem[];
    const uint32_t sb = smem_u32(smem);
    const int tid = threadIdx.x, wid = tid >> 5, lane = tid & 31;
    const int row0 = blockIdx.y * 128, col0 = blockIdx.x * 64;

    Ahi += (size_t)blockIdx.z * strA;  Alo += (size_t)blockIdx.z * strA;
    Bhi += (size_t)blockIdx.z * strB;  Blo += (size_t)blockIdx.z * strB;

    // 4m x 2n warp grid, 32x32 warp tiles
    const int wm = wid & 3, wn = wid >> 2;
    const int m0w = wm * 32, n0w = wn * 32;

    // ---- cp.async loader indexing (BK=16 -> 32B rows) ----
    const int la_row = tid >> 1;
    const int la_s   = tid & 1;
    const int lb_row = (tid & 127) >> 1;
    const int lb_s   = tid & 1;
    const bool do_b  = (tid < 128);

    // Hoisted: global pointers as u64 (cvta once)
    const unsigned long long pah = (unsigned long long)__cvta_generic_to_global(
        (const void*)(Ahi + (size_t)(row0 + la_row) * K + la_s * 8));
    const unsigned long long pal = (unsigned long long)__cvta_generic_to_global(
        (const void*)(Alo + (size_t)(row0 + la_row) * K + la_s * 8));
    const unsigned long long pbh = (unsigned long long)__cvta_generic_to_global(
        (const void*)(Bhi + (size_t)(col0 + lb_row) * K + lb_s * 8));
    const unsigned long long pbl = (unsigned long long)__cvta_generic_to_global(
        (const void*)(Blo + (size_t)(col0 + lb_row) * K + lb_s * 8));

    // Hoisted: swizzled store offsets
    const uint32_t swa = sw32((uint32_t)(la_row * 32 + la_s * 16));
    const uint32_t swb = sw32((uint32_t)(lb_row * 32 + lb_s * 16));

    // Hoisted: ldmatrix swizzled offsets (loop-invariant)
    const uint32_t a_lrow = (uint32_t)(lane & 15);
    const uint32_t a_lc16 = (uint32_t)(lane >> 4) * 16;
    const uint32_t b_lrow = (uint32_t)((lane & 7) + ((lane >> 4) & 1) * 8);
    const uint32_t b_lk16 = (uint32_t)((lane >> 3) & 1) * 16;
    const uint32_t offA0 = sw32((uint32_t)((m0w + a_lrow) * 32 + a_lc16));
    const uint32_t offA1 = sw32((uint32_t)((m0w + 16 + a_lrow) * 32 + a_lc16));
    const uint32_t offB0 = sw32((uint32_t)((n0w + b_lrow) * 32 + b_lk16));
    const uint32_t offB1 = sw32((uint32_t)((n0w + 16 + b_lrow) * 32 + b_lk16));

    // Hoisted: stage base addresses
    const uint32_t stage0 = sb;
    const uint32_t stage1 = sb + STAGE_B;
    const uint32_t stage2 = sb + 2 * STAGE_B;
    const uint32_t stage3 = sb + 3 * STAGE_B;

    float acc[2][4][4];
#pragma unroll
    for (int i = 0; i < 2; i++)
#pragma unroll
        for (int j = 0; j < 4; j++)
#pragma unroll
            for (int q = 0; q < 4; q++) acc[i][j][q] = 0.f;

    const int NCH = K >> 4;   // BK=16; 64 or 128 here (divisible by 4)

    auto issue = [&](int ch, uint32_t st) {
        if (ch < NCH) {
            const unsigned long long koff = (unsigned long long)(ch << 5);  // bytes
            CP_ASYNC16(st + AH_OFF + swa, pah + koff);
            CP_ASYNC16(st + AL_OFF + swa, pal + koff);
            if (do_b) {
                CP_ASYNC16(st + BH_OFF + swb, pbh + koff);
                CP_ASYNC16(st + BL_OFF + swb, pbl + koff);
            }
        }
        CP_COMMIT();
    };

    // One chunk (k16): 8 LDSM.x4 front-loaded -> 24 MMAs in 3 bursts of 8.
    auto mma_ks = [&](uint32_t base) {
        uint32_t aFh[2][4], bFh[4][2], bFl[4][2];
        ldsm_x4(aFh[0][0], aFh[0][1], aFh[0][2], aFh[0][3], base + AH_OFF + offA0);
        ldsm_x4(aFh[1][0], aFh[1][1], aFh[1][2], aFh[1][3], base + AH_OFF + offA1);
        {
            uint32_t r0, r1, r2, r3;
            ldsm_x4(r0, r1, r2, r3, base + BH_OFF + offB0);
            bFh[0][0] = r0; bFh[0][1] = r1; bFh[1][0] = r2; bFh[1][1] = r3;
            ldsm_x4(r0, r1, r2, r3, base + BH_OFF + offB1);
            bFh[2][0] = r0; bFh[2][1] = r1; bFh[3][0] = r2; bFh[3][1] = r3;
            ldsm_x4(r0, r1, r2, r3, base + BL_OFF + offB0);
            bFl[0][0] = r0; bFl[0][1] = r1; bFl[1][0] = r2; bFl[1][1] = r3;
            ldsm_x4(r0, r1, r2, r3, base + BL_OFF + offB1);
            bFl[2][0] = r0; bFl[2][1] = r1; bFl[3][0] = r2; bFl[3][1] = r3;
        }
        // burst 1: hh
#pragma unroll
        for (int mf = 0; mf < 2; mf++)
#pragma unroll
            for (int nf = 0; nf < 4; nf++) mma16816(acc[mf][nf], aFh[mf], bFh[nf]);
        // burst 2: hi(A) * lo(B)
#pragma unroll
        for (int mf = 0; mf < 2; mf++)
#pragma unroll
            for (int nf = 0; nf < 4; nf++) mma16816(acc[mf][nf], aFh[mf], bFl[nf]);
        // burst 3: lo(A) * hi(B)
        uint32_t aFl[2][4];
        ldsm_x4(aFl[0][0], aFl[0][1], aFl[0][2], aFl[0][3], base + AL_OFF + offA0);
        ldsm_x4(aFl[1][0], aFl[1][1], aFl[1][2], aFl[1][3], base + AL_OFF + offA1);
#pragma unroll
        for (int mf = 0; mf < 2; mf++)
#pragma unroll
            for (int nf = 0; nf < 4; nf++) mma16816(acc[mf][nf], aFl[mf], bFh[nf]);
    };

    // prologue: 3 stages in flight
    issue(0, stage0);
    issue(1, stage1);
    issue(2, stage2);

    const uint32_t stages[4] = {stage0, stage1, stage2, stage3};
    for (int ch4 = 0; ch4 < NCH; ch4 += 4) {
#pragma unroll
        for (int u = 0; u < 4; u++) {
            CP_WAIT2();
            __syncthreads();
            issue(ch4 + u + 3, stages[(u + 3) & 3]);
            mma_ks(stages[u]);
        }
    }
    CP_WAIT0();
    __syncthreads();

    // ---- epilogue: stage accums -> smem [128][68] -> coalesced writes ----
    float* eps = reinterpret_cast<float*>(smem);
    const int g = lane >> 2, c = lane & 3;
#pragma unroll
    for (int mf = 0; mf < 2; mf++)
#pragma unroll
        for (int nf = 0; nf < 4; nf++) {
            int r  = m0w + mf * 16 + g;
            int cc = n0w + nf * 8 + 2 * c;
            *reinterpret_cast<float2*>(&eps[r * 68 + cc]) =
                make_float2(acc[mf][nf][0], acc[mf][nf][1]);
            *reinterpret_cast<float2*>(&eps[(r + 8) * 68 + cc]) =
                make_float2(acc[mf][nf][2], acc[mf][nf][3]);
        }
    __syncthreads();

    if (Chi) {
        __nv_bfloat16* ph = Chi + (size_t)blockIdx.z * strC;
        __nv_bfloat16* pl = Clo + (size_t)blockIdx.z * strC;
#pragma unroll
        for (int it = 0; it < 8; it++) {
            int idx = tid + it * 256;
            int row = idx >> 4;
            int c4  = (idx & 15) << 2;
            float4 v = *reinterpret_cast<float4*>(&eps[row * 68 + c4]);
            float4 bz = *reinterpret_cast<const float4*>(&bias[col0 + c4]);
            v.x += bz.x; v.y += bz.y; v.z += bz.z; v.w += bz.w;
            uint2 hi, lo;
            split2(v, hi, lo);
            size_t o = (size_t)(row0 + row) * N + col0 + c4;
            *reinterpret_cast<uint2*>(&ph[o]) = hi;
            *reinterpret_cast<uint2*>(&pl[o]) = lo;
        }
    } else {
        float* Cb = C + (size_t)blockIdx.z * strC;
#pragma unroll
        for (int it = 0; it < 8; it++) {
            int idx = tid + it * 256;
            int row = idx >> 4;
            int c4  = (idx & 15) << 2;
            float4 v = *reinterpret_cast<float4*>(&eps[row * 68 + c4]);
            *reinterpret_cast<float4*>(&Cb[(size_t)(row0 + row) * N + col0 + c4]) = v;
        }
    }
}

// ============================================================
// prep_x (R17: vectorized): X -> X_hi/X_lo + XT_hi/XT_lo
// 256 flat threads; float4 loads (128B/warp-row), uint2 stores,
// pad-33 smem transpose (store banks sr+4*dq and read banks sq+dr
// both cover 32 distinct banks -> conflict-free).
// ============================================================
__global__ __launch_bounds__(256) void prep_x(
    const float* __restrict__ X,
    __nv_bfloat16* __restrict__ Xhi, __nv_bfloat16* __restrict__ Xlo,
    __nv_bfloat16* __restrict__ XThi, __nv_bfloat16* __restrict__ XTlo)
{
    __shared__ float t[32][33];
    const int b = blockIdx.z;
    const int s0 = blockIdx.x * 32, d0 = blockIdx.y * 32;
    const size_t bo = (size_t)b * SS * DD;
    const int tid = threadIdx.x;
    const int sr = tid >> 3;          // 0..31 : s row
    const int dq = (tid & 7) * 4;     // 0,4,..28 : d col (float4)

    // Load one float4 (warp = 4 rows x 128B, fully coalesced)
    float4 v = *reinterpret_cast<const float4*>(
        &X[bo + (size_t)(s0 + sr) * DD + d0 + dq]);

    // smem stage for transpose (scalar stores; banks sr+4*dq_idx distinct)
    t[sr][dq + 0] = v.x;
    t[sr][dq + 1] = v.y;
    t[sr][dq + 2] = v.z;
    t[sr][dq + 3] = v.w;

    // direct split store
    uint2 hi, lo;
    split2(v, hi, lo);
    {
        size_t o = bo + (size_t)(s0 + sr) * DD + d0 + dq;
        *reinterpret_cast<uint2*>(&Xhi[o]) = hi;
        *reinterpret_cast<uint2*>(&Xlo[o]) = lo;
    }
    __syncthreads();

    // transpose: thread covers d row = sr, s quad = dq
    const int dr = sr;
    const int sq = dq;
    float4 w;
    w.x = t[sq + 0][dr];
    w.y = t[sq + 1][dr];
    w.z = t[sq + 2][dr];
    w.w = t[sq + 3][dr];
    split2(w, hi, lo);
    size_t ot = bo + (size_t)(d0 + dr) * SS + s0 + sq;
    *reinterpret_cast<uint2*>(&XThi[ot]) = hi;
    *reinterpret_cast<uint2*>(&XTlo[ot]) = lo;
}

__global__ __launch_bounds__(256) void split_w(
    const float* __restrict__ W,
    __nv_bfloat16* __restrict__ Whi, __nv_bfloat16* __restrict__ Wlo)
{
    int idx = blockIdx.x * 256 + threadIdx.x;
    float4 v = reinterpret_cast<const float4*>(W)[idx];
    uint2 hi, lo;
    split2(v, hi, lo);
    reinterpret_cast<uint2*>(Whi)[idx] = hi;
    reinterpret_cast<uint2*>(Wlo)[idx] = lo;
}

// ============================================================
// In-place row softmax + split bf16 out
// ============================================================
__device__ __forceinline__ float warp_max(float v) {
#pragma unroll
    for (int o = 16; o > 0; o >>= 1) v = fmaxf(v, __shfl_xor_sync(0xFFFFFFFFu, v, o));
    return v;
}
__device__ __forceinline__ float warp_sum(float v) {
#pragma unroll
    for (int o = 16; o > 0; o >>= 1) v += __shfl_xor_sync(0xFFFFFFFFu, v, o);
    return v;
}

__global__ __launch_bounds__(256) void softmax_rows(
    float* __restrict__ attn,
    __nv_bfloat16* __restrict__ Ahi, __nv_bfloat16* __restrict__ Alo)
{
    __shared__ float red[8];
    const size_t ro = (size_t)blockIdx.x * SS;
    float* row = attn + ro;
    const int tid = threadIdx.x, lane = tid & 31, wid = tid >> 5;

    float4 v[2];
    v[0] = *reinterpret_cast<const float4*>(&row[tid * 4]);
    v[1] = *reinterpret_cast<const float4*>(&row[(tid + 256) * 4]);

    float mx = -INFINITY;
#pragma unroll
    for (int i = 0; i < 2; i++)
        mx = fmaxf(mx, fmaxf(fmaxf(v[i].x, v[i].y), fmaxf(v[i].z, v[i].w)));
    mx = warp_max(mx);
    if (lane == 0) red[wid] = mx;
    __syncthreads();
    if (wid == 0) {
        float t = (lane < 8) ? red[lane] : -INFINITY;
        t = warp_max(t);
        if (lane == 0) red[0] = t;
    }
    __syncthreads();
    mx = red[0];
    __syncthreads();

    float s = 0.f;
#pragma unroll
    for (int i = 0; i < 2; i++) {
        v[i].x = expf(v[i].x - mx); s += v[i].x;
        v[i].y = expf(v[i].y - mx); s += v[i].y;
        v[i].z = expf(v[i].z - mx); s += v[i].z;
        v[i].w = expf(v[i].w - mx); s += v[i].w;
    }
    s = warp_sum(s);
    if (lane == 0) red[wid] = s;
    __syncthreads();
    if (wid == 0) {
        float t = (lane < 8) ? red[lane] : 0.0f;
        t = warp_sum(t);
        if (lane == 0) red[0] = t;
    }
    __syncthreads();
    float inv = 1.0f / red[0];

#pragma unroll
    for (int i = 0; i < 2; i++) { v[i].x *= inv; v[i].y *= inv; v[i].z *= inv; v[i].w *= inv; }
    *reinterpret_cast<float4*>(&row[tid * 4])         = v[0];
    *reinterpret_cast<float4*>(&row[(tid + 256) * 4]) = v[1];

    uint2 hi, lo;
    split2(v[0], hi, lo);
    *reinterpret_cast<uint2*>(&Ahi[ro + tid * 4]) = hi;
    *reinterpret_cast<uint2*>(&Alo[ro + tid * 4]) = lo;
    split2(v[1], hi, lo);
    *reinterpret_cast<uint2*>(&Ahi[ro + (tid + 256) * 4]) = hi;
    *reinterpret_cast<uint2*>(&Alo[ro + (tid + 256) * 4]) = lo;
}

// ============================================================
// kernel_launch
// ============================================================
extern "C" void kernel_launch(void* const* d_in, const int* in_sizes, int n_in,
                              void* d_out, int out_size)
{
    const float* X    = (const float*)d_in[0];
    const float* W    = (const float*)d_in[1];
    const float* bias = (const float*)d_in[2];

    float* ctx  = (float*)d_out;                           // [8,2048,1024]
    float* attn = (float*)d_out + (size_t)BB * SS * DD;    // [8,2048,2048]

    __nv_bfloat16 *xhi, *xlo, *xthi, *xtlo, *whi, *wlo, *phi, *plo, *ahi, *alo;
    cudaGetSymbolAddress((void**)&xhi,  g_xhi);
    cudaGetSymbolAddress((void**)&xlo,  g_xlo);
    cudaGetSymbolAddress((void**)&xthi, g_xthi);
    cudaGetSymbolAddress((void**)&xtlo, g_xtlo);
    cudaGetSymbolAddress((void**)&whi,  g_whi);
    cudaGetSymbolAddress((void**)&wlo,  g_wlo);
    cudaGetSymbolAddress((void**)&phi,  g_phi);
    cudaGetSymbolAddress((void**)&plo,  g_plo);
    cudaGetSymbolAddress((void**)&ahi,  g_ahi);
    cudaGetSymbolAddress((void**)&alo,  g_alo);

    cudaFuncSetAttribute(gemm_nt_mma, cudaFuncAttributeMaxDynamicSharedMemorySize, GEMM_SMEM);

    const long long sXD = (long long)SS * DD;
    const long long sAA = (long long)SS * SS;

    {
        dim3 grid(SS / 32, DD / 32, BB);
        prep_x<<<grid, 256>>>(X, xhi, xlo, xthi, xtlo);
    }
    split_w<<<(DD * DD / 4) / 256, 256>>>(W, whi, wlo);

    // GEMM1: proj = X * W^T + b  -> split bf16 pair
    {
        dim3 grid(DD / 64, (BB * SS) / 128, 1);
        gemm_nt_mma<<<grid, 256, GEMM_SMEM>>>(xhi, xlo, whi, wlo,
                                              nullptr, phi, plo, bias,
                                              BB * SS, DD, DD, 0, 0, 0);
    }
    // GEMM2: attn[b] = X[b] * proj[b]^T  (fp32 out)
    {
        dim3 grid(SS / 64, SS / 128, BB);
        gemm_nt_mma<<<grid, 256, GEMM_SMEM>>>(xhi, xlo, phi, plo,
                                              attn, nullptr, nullptr, nullptr,
                                              SS, SS, DD, sXD, sXD, sAA);
    }
    softmax_rows<<<BB * SS, 256>>>(attn, ahi, alo);
    // GEMM3: ctx[b] = attn[b] * XT[b]^T  (fp32 out)
    {
        dim3 grid(DD / 64, SS / 128, BB);
        gemm_nt_mma<<<grid, 256, GEMM_SMEM>>>(ahi, alo, xthi, xtlo,
                                              ctx, nullptr, nullptr, nullptr,
                                              SS, DD, SS, sAA, sXD, sXD);
    }
}